// round 1
// baseline (speedup 1.0000x reference)
#include <cuda_runtime.h>

typedef unsigned long long u64;

#define TT 2048
#define BB 32
#define HH 256
#define MROWS (TT*BB)      // 65536
#define LANES (BB*HH)      // 8192
#define NCH 64
#define CLEN (TT/NCH)      // 32

// ---------------- scratch (static device globals; no cudaMalloc allowed) ---
__device__ float g_x0[(size_t)MROWS*HH];          // LN0 output [T,B,256]
__device__ float g_f0[2][(size_t)MROWS*HH];       // layer0 gates per dir
__device__ float g_z0[2][(size_t)MROWS*HH];
__device__ float g_r0[2][(size_t)MROWS*HH];
__device__ float g_h1[(size_t)MROWS*2*HH];        // [T,B,512]
__device__ float g_x1[(size_t)MROWS*2*HH];        // LN1 output
__device__ float g_f1[(size_t)MROWS*HH];          // layer1 fwd gates
__device__ float g_z1[(size_t)MROWS*HH];
__device__ float g_cA0[2][NCH*LANES];
__device__ float g_cB0[2][NCH*LANES];
__device__ float g_cin0[2][NCH*LANES];
__device__ float g_cA1[NCH*LANES];
__device__ float g_cB1[NCH*LANES];
__device__ float g_cfin[LANES];
__device__ float g_h2[BB*2*HH];

// ---------------- helpers ---------------------------------------------------
__device__ __forceinline__ u64 pack2(float lo, float hi) {
    u64 r; asm("mov.b64 %0, {%1, %2};" : "=l"(r) : "f"(lo), "f"(hi)); return r;
}
__device__ __forceinline__ float2 unpack2(u64 v) {
    float2 r; asm("mov.b64 {%0, %1}, %2;" : "=f"(r.x), "=f"(r.y) : "l"(v)); return r;
}
__device__ __forceinline__ u64 ffma2(u64 a, u64 b, u64 c) {
    u64 d; asm("fma.rn.f32x2 %0, %1, %2, %3;" : "=l"(d) : "l"(a), "l"(b), "l"(c)); return d;
}
__device__ __forceinline__ float sigmf(float x) {
    return 1.0f / (1.0f + __expf(-x));
}

// ---------------- LayerNorm (warp per row) ----------------------------------
// WHICH==0: in = src arg (raw x), out = g_x0.  WHICH==1: in = g_h1, out = g_x1.
template<int C, int WHICH>
__global__ void ln_kernel(const float* __restrict__ src,
                          const float* __restrict__ gam,
                          const float* __restrict__ bet)
{
    const float* in  = (WHICH == 0) ? src  : g_h1;
    float*       out = (WHICH == 0) ? g_x0 : g_x1;
    int warp = threadIdx.x >> 5, lane = threadIdx.x & 31;
    size_t row = (size_t)blockIdx.x * 8 + warp;
    const float* x = in + row * C;
    constexpr int NV = C / 32;
    float v[NV], s = 0.f, s2 = 0.f;
#pragma unroll
    for (int i = 0; i < NV; i++) {
        float t = x[lane + 32*i];
        v[i] = t; s += t; s2 += t * t;
    }
#pragma unroll
    for (int o = 16; o; o >>= 1) {
        s  += __shfl_xor_sync(0xffffffffu, s,  o);
        s2 += __shfl_xor_sync(0xffffffffu, s2, o);
    }
    float m   = s  * (1.0f / C);
    float var = s2 * (1.0f / C) - m * m;
    float inv = rsqrtf(var + 1e-5f);
    float* y = out + row * C;
#pragma unroll
    for (int i = 0; i < NV; i++) {
        int c = lane + 32*i;
        y[c] = (v[i] - m) * inv * gam[c] + bet[c];
    }
}

// ---------------- Fused GEMM + gate epilogue --------------------------------
// Computes, for each (m, h): xt = A[m,:]·W[:,h], fp = A[m,:]·W[:,H+h],
// (rp = A[m,:]·W[:,2H+h] if NG==3); then f=sig(fp+bf), z=(1-f)*xt, r=sig(rp+br).
// NG==3: layer0 (A=g_x0, KD=256, outputs g_{f,z,r}0[dir]).
// NG==2: layer1 fwd (A=g_x1, KD=512, outputs g_f1,g_z1).
// Block tile: 128(M) x 64(H) x NG groups.  Thread: 8(M) x 4(H) x NG via f32x2.
template<int NG, int KD>
__global__ __launch_bounds__(256) void gemm_gates(
    const float* __restrict__ W,
    const float* __restrict__ bfp,
    const float* __restrict__ brp,
    int dir)
{
    const float* A;
    float *fo, *zo, *ro;
    if (NG == 3) { A = g_x0; fo = g_f0[dir]; zo = g_z0[dir]; ro = g_r0[dir]; }
    else         { A = g_x1; fo = g_f1;      zo = g_z1;      ro = nullptr;   }

    constexpr int BK = 16;
    __shared__ float As[BK][128 + 4];
    __shared__ float Ws[BK][NG * 64];

    int tid = threadIdx.x;
    int tx = tid & 15, ty = tid >> 4;
    int m0 = blockIdx.y * 128, h0 = blockIdx.x * 64;

    u64 acc[8][NG][2];
#pragma unroll
    for (int i = 0; i < 8; i++)
#pragma unroll
        for (int g = 0; g < NG; g++) { acc[i][g][0] = 0ull; acc[i][g][1] = 0ull; }

    for (int k0 = 0; k0 < KD; k0 += BK) {
        // A tile: 128 rows x 16 cols, stored transposed As[k][m]
#pragma unroll
        for (int q = 0; q < 2; q++) {
            int s = tid + q * 256;
            int r = s >> 2, c = s & 3;
            float4 av = *reinterpret_cast<const float4*>(
                A + (size_t)(m0 + r) * KD + (k0 + c * 4));
            As[c*4+0][r] = av.x; As[c*4+1][r] = av.y;
            As[c*4+2][r] = av.z; As[c*4+3][r] = av.w;
        }
        // W tile: 16 rows x (NG groups x 64 cols)
#pragma unroll
        for (int q = 0; q < NG; q++) {
            int s = tid + q * 256;
            int kk = s / (NG * 16);
            int rem = s - kk * (NG * 16);
            int g = rem >> 4, h4 = rem & 15;
            float4 wv = *reinterpret_cast<const float4*>(
                W + (size_t)(k0 + kk) * (3 * HH) + g * HH + h0 + h4 * 4);
            *reinterpret_cast<float4*>(&Ws[kk][g * 64 + h4 * 4]) = wv;
        }
        __syncthreads();
#pragma unroll
        for (int k = 0; k < BK; k++) {
            float4 a0 = *reinterpret_cast<const float4*>(&As[k][ty * 8]);
            float4 a1 = *reinterpret_cast<const float4*>(&As[k][ty * 8 + 4]);
            u64 a2[8];
            a2[0] = pack2(a0.x, a0.x); a2[1] = pack2(a0.y, a0.y);
            a2[2] = pack2(a0.z, a0.z); a2[3] = pack2(a0.w, a0.w);
            a2[4] = pack2(a1.x, a1.x); a2[5] = pack2(a1.y, a1.y);
            a2[6] = pack2(a1.z, a1.z); a2[7] = pack2(a1.w, a1.w);
#pragma unroll
            for (int g = 0; g < NG; g++) {
                const u64* wp = reinterpret_cast<const u64*>(&Ws[k][g * 64 + tx * 4]);
                u64 w0 = wp[0], w1 = wp[1];
#pragma unroll
                for (int i = 0; i < 8; i++) {
                    acc[i][g][0] = ffma2(a2[i], w0, acc[i][g][0]);
                    acc[i][g][1] = ffma2(a2[i], w1, acc[i][g][1]);
                }
            }
        }
        __syncthreads();
    }

    int hbase = h0 + tx * 4;
    float4 bf4 = *reinterpret_cast<const float4*>(bfp + hbase);
    float bfa[4] = {bf4.x, bf4.y, bf4.z, bf4.w};
#pragma unroll
    for (int i = 0; i < 8; i++) {
        size_t m = (size_t)(m0 + ty * 8 + i);
        size_t base = m * HH + hbase;
        float2 x01 = unpack2(acc[i][0][0]), x23 = unpack2(acc[i][0][1]);
        float2 p01 = unpack2(acc[i][1][0]), p23 = unpack2(acc[i][1][1]);
        float xt[4] = {x01.x, x01.y, x23.x, x23.y};
        float fp[4] = {p01.x, p01.y, p23.x, p23.y};
        float fg[4], zg[4];
#pragma unroll
        for (int j = 0; j < 4; j++) {
            fg[j] = sigmf(fp[j] + bfa[j]);
            zg[j] = (1.0f - fg[j]) * xt[j];
        }
        *reinterpret_cast<float4*>(fo + base) = make_float4(fg[0], fg[1], fg[2], fg[3]);
        *reinterpret_cast<float4*>(zo + base) = make_float4(zg[0], zg[1], zg[2], zg[3]);
        if (NG == 3) {
            float4 br4 = *reinterpret_cast<const float4*>(brp + hbase);
            float2 r01 = unpack2(acc[i][2][0]), r23 = unpack2(acc[i][2][1]);
            float rp[4] = {r01.x, r01.y, r23.x, r23.y};
            float bra[4] = {br4.x, br4.y, br4.z, br4.w};
            float rg[4];
#pragma unroll
            for (int j = 0; j < 4; j++) rg[j] = sigmf(rp[j] + bra[j]);
            *reinterpret_cast<float4*>(ro + base) = make_float4(rg[0], rg[1], rg[2], rg[3]);
        }
    }
}

// ---------------- Chunked scans ---------------------------------------------
// c_t = f_t * c_{t-1} + z_t over T, split into NCH chunks of CLEN.
// dir 0 = forward (t = j*CLEN+s), dir 1 = backward (t = T-1-(j*CLEN+s)).

__global__ void scan0_A() {
    int l = blockIdx.x * blockDim.x + threadIdx.x;
    int dj = blockIdx.y; int dir = dj >> 6; int j = dj & 63;
    const float* F = g_f0[dir];
    const float* Z = g_z0[dir];
    float a = 1.f, c = 0.f;
    int tb = j * CLEN;
#pragma unroll 8
    for (int s = 0; s < CLEN; s++) {
        int t = dir ? (TT - 1 - (tb + s)) : (tb + s);
        size_t idx = (size_t)t * LANES + l;
        float fv = F[idx], zv = Z[idx];
        c = fmaf(fv, c, zv);
        a *= fv;
    }
    g_cA0[dir][j * LANES + l] = a;
    g_cB0[dir][j * LANES + l] = c;
}

__global__ void scan0_B(const float* __restrict__ c0) {
    int gi = blockIdx.x * blockDim.x + threadIdx.x;
    int dir = gi >> 13;
    int l = gi & (LANES - 1);
    float c = c0[dir * LANES + l];
#pragma unroll 8
    for (int j = 0; j < NCH; j++) {
        int o = j * LANES + l;
        g_cin0[dir][o] = c;
        c = fmaf(g_cA0[dir][o], c, g_cB0[dir][o]);
    }
}

__global__ void scan0_C() {
    int l = blockIdx.x * blockDim.x + threadIdx.x;
    int dj = blockIdx.y; int dir = dj >> 6; int j = dj & 63;
    const float* F = g_f0[dir];
    const float* Z = g_z0[dir];
    const float* R = g_r0[dir];
    float c = g_cin0[dir][j * LANES + l];
    int b = l >> 8, h = l & 255;
    int tb = j * CLEN;
#pragma unroll 4
    for (int s = 0; s < CLEN; s++) {
        int t = dir ? (TT - 1 - (tb + s)) : (tb + s);
        size_t idx = (size_t)t * LANES + l;
        c = fmaf(F[idx], c, Z[idx]);
        float r = R[idx];
        float sk = g_x0[idx];
        g_h1[(size_t)t * (BB * 2 * HH) + (size_t)b * (2 * HH) + dir * HH + h]
            = r * c + (1.0f - r) * sk;
    }
}

__global__ void scan1_A() {
    int l = blockIdx.x * blockDim.x + threadIdx.x;
    int j = blockIdx.y;
    float a = 1.f, c = 0.f;
    int tb = j * CLEN;
#pragma unroll 8
    for (int s = 0; s < CLEN; s++) {
        size_t idx = (size_t)(tb + s) * LANES + l;
        float fv = g_f1[idx], zv = g_z1[idx];
        c = fmaf(fv, c, zv);
        a *= fv;
    }
    g_cA1[j * LANES + l] = a;
    g_cB1[j * LANES + l] = c;
}

__global__ void scan1_B(const float* __restrict__ c0) {
    int l = blockIdx.x * blockDim.x + threadIdx.x;
    float c = c0[2 * LANES + l];
#pragma unroll 8
    for (int j = 0; j < NCH; j++) {
        int o = j * LANES + l;
        c = fmaf(g_cA1[o], c, g_cB1[o]);
    }
    g_cfin[l] = c;
}

// ---------------- Tail: t = T-1 of layer 1 (both dirs) -----------------------
__global__ void tail_h2(const float* __restrict__ W1f,  const float* __restrict__ Wh1f,
                        const float* __restrict__ br1f,
                        const float* __restrict__ W1b,  const float* __restrict__ Wh1b,
                        const float* __restrict__ bf1b, const float* __restrict__ br1b,
                        const float* __restrict__ c0)
{
    __shared__ float xr[2 * HH];
    int b = blockIdx.x;
    int tid = threadIdx.x;
    xr[tid] = g_x1[(size_t)((TT - 1) * BB + b) * (2 * HH) + tid];
    __syncthreads();
    int h = tid;
    if (h < HH) {
        // forward dir: need r and projected skip at t=T-1 only
        float ar = 0.f, as = 0.f;
        for (int k = 0; k < 2 * HH; k++) {
            float xv = xr[k];
            ar = fmaf(xv, W1f[k * (3 * HH) + 2 * HH + h], ar);
            as = fmaf(xv, Wh1f[k * HH + h], as);
        }
        float r = sigmf(ar + br1f[h]);
        g_h2[b * (2 * HH) + h] = r * g_cfin[b * HH + h] + (1.0f - r) * as;
    } else {
        // backward dir: cs[T-1] = f*c0 + z at last step only
        int hb = h - HH;
        float a0 = 0.f, a1 = 0.f, a2v = 0.f, as = 0.f;
        for (int k = 0; k < 2 * HH; k++) {
            float xv = xr[k];
            a0  = fmaf(xv, W1b[k * (3 * HH) + hb],          a0);
            a1  = fmaf(xv, W1b[k * (3 * HH) + HH + hb],     a1);
            a2v = fmaf(xv, W1b[k * (3 * HH) + 2 * HH + hb], a2v);
            as  = fmaf(xv, Wh1b[k * HH + hb],               as);
        }
        float f = sigmf(a1 + bf1b[hb]);
        float r = sigmf(a2v + br1b[hb]);
        float c = f * c0[3 * LANES + b * HH + hb] + (1.0f - f) * a0;
        g_h2[b * (2 * HH) + h] = r * c + (1.0f - r) * as;
    }
}

__global__ void tail_out(const float* __restrict__ Wfc,
                         const float* __restrict__ bfc,
                         float* __restrict__ out)
{
    int tid = threadIdx.x;       // 64 threads: (b, o)
    int b = tid >> 1, o = tid & 1;
    float acc = bfc[o];
    for (int k = 0; k < 2 * HH; k++)
        acc = fmaf(g_h2[b * (2 * HH) + k], Wfc[k * 2 + o], acc);
    out[b * 2 + o] = acc;
}

// ---------------- launch -----------------------------------------------------
extern "C" void kernel_launch(void* const* d_in, const int* in_sizes, int n_in,
                              void* d_out, int out_size)
{
    const float* x     = (const float*)d_in[0];
    const float* c0    = (const float*)d_in[1];
    const float* ln0_g = (const float*)d_in[2];
    const float* ln0_b = (const float*)d_in[3];
    const float* ln1_g = (const float*)d_in[4];
    const float* ln1_b = (const float*)d_in[5];
    const float* W0f   = (const float*)d_in[6];
    const float* bf0f  = (const float*)d_in[7];
    const float* br0f  = (const float*)d_in[8];
    const float* W0b   = (const float*)d_in[9];
    const float* bf0b  = (const float*)d_in[10];
    const float* br0b  = (const float*)d_in[11];
    const float* W1f   = (const float*)d_in[12];
    const float* Wh1f  = (const float*)d_in[13];
    const float* bf1f  = (const float*)d_in[14];
    const float* br1f  = (const float*)d_in[15];
    const float* W1b   = (const float*)d_in[16];
    const float* Wh1b  = (const float*)d_in[17];
    const float* bf1b  = (const float*)d_in[18];
    const float* br1b  = (const float*)d_in[19];
    const float* Wfc   = (const float*)d_in[20];
    const float* bfc   = (const float*)d_in[21];
    float* out = (float*)d_out;

    dim3 gln(MROWS / 8);
    dim3 gg(HH / 64, MROWS / 128);

    // layer 0
    ln_kernel<256, 0><<<gln, 256>>>(x, ln0_g, ln0_b);
    gemm_gates<3, 256><<<gg, 256>>>(W0f, bf0f, br0f, 0);
    gemm_gates<3, 256><<<gg, 256>>>(W0b, bf0b, br0b, 1);
    scan0_A<<<dim3(LANES / 256, 2 * NCH), 256>>>();
    scan0_B<<<(2 * LANES) / 256, 256>>>(c0);
    scan0_C<<<dim3(LANES / 256, 2 * NCH), 256>>>();

    // layer 1
    ln_kernel<512, 1><<<gln, 256>>>(nullptr, ln1_g, ln1_b);
    gemm_gates<2, 512><<<gg, 256>>>(W1f, bf1f, bf1f /*unused*/, 0);
    scan1_A<<<dim3(LANES / 256, NCH), 256>>>();
    scan1_B<<<LANES / 256, 256>>>(c0);

    // tail + head
    tail_h2<<<BB, 2 * HH>>>(W1f, Wh1f, br1f, W1b, Wh1b, bf1b, br1b, c0);
    tail_out<<<1, 64>>>(Wfc, bfc, out);
}

// round 3
// speedup vs baseline: 1.6226x; 1.6226x over previous
#include <cuda_runtime.h>
#include <cuda_bf16.h>
#include <cstdint>

typedef unsigned long long u64;
typedef unsigned int u32;

#define TT 2048
#define BB 32
#define HH 256
#define MROWS (TT*BB)      // 65536
#define LANES (BB*HH)      // 8192
#define NCH 64
#define CLEN (TT/NCH)      // 32

// ---------------- scratch (static device globals) ---------------------------
__device__ __align__(16) __nv_bfloat16 g_x0h[(size_t)MROWS*HH];
__device__ __align__(16) __nv_bfloat16 g_x0l[(size_t)MROWS*HH];
__device__ __align__(16) __nv_bfloat16 g_x1h[(size_t)MROWS*2*HH];
__device__ __align__(16) __nv_bfloat16 g_x1l[(size_t)MROWS*2*HH];
__device__ __align__(16) float g_U0[(size_t)MROWS*1536];   // [m][dir*768 + {xt:h, fp:256+h, rp:512+h}]
__device__ __align__(16) float g_U1[(size_t)MROWS*512];    // [m][{xt:h, fp:256+h}]
__device__ float g_h1[(size_t)MROWS*2*HH];
__device__ float g_cA0[2][NCH*LANES];
__device__ float g_cB0[2][NCH*LANES];
__device__ float g_cin0[2][NCH*LANES];
__device__ float g_cA1[NCH*LANES];
__device__ float g_cB1[NCH*LANES];
__device__ float g_cfin[LANES];
__device__ float g_h2[BB*2*HH];
// transposed hi/lo weights [N][K]
__device__ __align__(16) __nv_bfloat16 g_w0h[1536*256];
__device__ __align__(16) __nv_bfloat16 g_w0l[1536*256];
__device__ __align__(16) __nv_bfloat16 g_w1h[512*512];
__device__ __align__(16) __nv_bfloat16 g_w1l[512*512];

// ---------------- PTX helpers ------------------------------------------------
__device__ __forceinline__ u32 smem_u32(const void* p) {
    u32 a;
    asm("{ .reg .u64 t; cvta.to.shared.u64 t, %1; cvt.u32.u64 %0, t; }"
        : "=r"(a) : "l"(p));
    return a;
}
__device__ __forceinline__ void cp16(u32 dst, const void* src) {
    asm volatile("cp.async.ca.shared.global [%0], [%1], 16;"
                 :: "r"(dst), "l"(src) : "memory");
}
__device__ __forceinline__ void ldm4(u32 a, u32& r0, u32& r1, u32& r2, u32& r3) {
    asm volatile("ldmatrix.sync.aligned.m8n8.x4.shared.b16 {%0,%1,%2,%3}, [%4];"
                 : "=r"(r0), "=r"(r1), "=r"(r2), "=r"(r3) : "r"(a));
}
__device__ __forceinline__ void mma16816(float* c, const u32* a, const u32* b) {
    asm volatile(
        "mma.sync.aligned.m16n8k16.row.col.f32.bf16.bf16.f32 "
        "{%0,%1,%2,%3}, {%4,%5,%6,%7}, {%8,%9}, {%0,%1,%2,%3};"
        : "+f"(c[0]), "+f"(c[1]), "+f"(c[2]), "+f"(c[3])
        : "r"(a[0]), "r"(a[1]), "r"(a[2]), "r"(a[3]), "r"(b[0]), "r"(b[1]));
}
__device__ __forceinline__ float sigmf(float x) { return 1.0f / (1.0f + __expf(-x)); }

// ---------------- weight transpose + hi/lo split -----------------------------
__global__ void conv_w(const float* __restrict__ W0f, const float* __restrict__ W0b,
                       const float* __restrict__ W1f)
{
    int i = blockIdx.x * blockDim.x + threadIdx.x;
    const int SZ0 = 1536 * 256;
    float v;
    __nv_bfloat16 *oh, *ol;
    int oi;
    if (i < SZ0) {
        int n = i >> 8, k = i & 255;
        int dir = n / 768, nn = n - dir * 768;
        const float* src = dir ? W0b : W0f;
        v = src[k * 768 + nn];
        oh = g_w0h; ol = g_w0l; oi = i;
    } else {
        int j = i - SZ0;
        int n = j >> 9, k = j & 511;
        v = W1f[k * 768 + n];     // only first 512 cols (xt, fp) needed
        oh = g_w1h; ol = g_w1l; oi = j;
    }
    __nv_bfloat16 hi = __float2bfloat16_rn(v);
    __nv_bfloat16 lo = __float2bfloat16_rn(v - __bfloat162float(hi));
    oh[oi] = hi; ol[oi] = lo;
}

// ---------------- LayerNorm -> hi/lo bf16 ------------------------------------
template<int C, int WHICH>
__global__ void ln_kernel(const float* __restrict__ src,
                          const float* __restrict__ gam,
                          const float* __restrict__ bet)
{
    const float* in = (WHICH == 0) ? src : g_h1;
    __nv_bfloat16* oh = (WHICH == 0) ? g_x0h : g_x1h;
    __nv_bfloat16* ol = (WHICH == 0) ? g_x0l : g_x1l;
    int warp = threadIdx.x >> 5, lane = threadIdx.x & 31;
    size_t row = (size_t)blockIdx.x * 8 + warp;
    const float* x = in + row * C;
    constexpr int NV = C / 32;
    float v[NV], s = 0.f, s2 = 0.f;
#pragma unroll
    for (int i = 0; i < NV; i++) {
        float t = x[lane + 32 * i];
        v[i] = t; s += t; s2 += t * t;
    }
#pragma unroll
    for (int o = 16; o; o >>= 1) {
        s  += __shfl_xor_sync(0xffffffffu, s,  o);
        s2 += __shfl_xor_sync(0xffffffffu, s2, o);
    }
    float m   = s  * (1.0f / C);
    float var = s2 * (1.0f / C) - m * m;
    float inv = rsqrtf(var + 1e-5f);
#pragma unroll
    for (int i = 0; i < NV; i++) {
        int c = lane + 32 * i;
        float y = (v[i] - m) * inv * gam[c] + bet[c];
        __nv_bfloat16 hi = __float2bfloat16_rn(y);
        __nv_bfloat16 lo = __float2bfloat16_rn(y - __bfloat162float(hi));
        oh[row * C + c] = hi;
        ol[row * C + c] = lo;
    }
}

// ---------------- HMMA GEMM (mma.sync bf16, 3-term hi/lo split) --------------
// C[M, NT] = A[M, K] * B^T,  B stored [NT][K].  Block 128x128x32, 8 warps.
// SMEM per stage: 4 arrays (Ah, Al, Bh, Bl) of 128 rows x 80B (64B data + pad).
template<int LAYER>
__global__ __launch_bounds__(256) void gemm_hmma()
{
    constexpr int KDIM = (LAYER == 0) ? 256 : 512;
    constexpr int NT   = (LAYER == 0) ? 1536 : 512;
    constexpr int NK   = KDIM / 32;
    constexpr int ARR  = 10240;          // 128*80
    constexpr int STG  = 4 * ARR;        // 40960 per stage

    const __nv_bfloat16* Ah = (LAYER == 0) ? g_x0h : g_x1h;
    const __nv_bfloat16* Al = (LAYER == 0) ? g_x0l : g_x1l;
    const __nv_bfloat16* Bh = (LAYER == 0) ? g_w0h : g_w1h;
    const __nv_bfloat16* Bl = (LAYER == 0) ? g_w0l : g_w1l;
    float* U = (LAYER == 0) ? g_U0 : g_U1;

    extern __shared__ char smraw[];
    const int tid = threadIdx.x, lane = tid & 31, wid = tid >> 5;
    const int wm = wid & 1, wn = wid >> 1;
    const int m0 = blockIdx.y * 128, n0 = blockIdx.x * 128;
    const u32 sb = smem_u32(smraw);

    float acc[4][4][4];
#pragma unroll
    for (int s = 0; s < 4; s++)
#pragma unroll
        for (int n = 0; n < 4; n++)
#pragma unroll
            for (int e = 0; e < 4; e++) acc[s][n][e] = 0.f;

    // stage loader: 2 x 16B per thread per array
    auto load_stage = [&](int st) {
        u32 dst = sb + (st & 1) * STG;
        int kb = st * 32;
#pragma unroll
        for (int q = 0; q < 2; q++) {
            int id = tid + q * 256;
            int row = id >> 2, ch = id & 3;
            u32 off = row * 80 + ch * 16;
            size_t ga = (size_t)(m0 + row) * KDIM + kb + ch * 8;
            size_t gb = (size_t)(n0 + row) * KDIM + kb + ch * 8;
            cp16(dst + off,           Ah + ga);
            cp16(dst + ARR + off,     Al + ga);
            cp16(dst + 2 * ARR + off, Bh + gb);
            cp16(dst + 3 * ARR + off, Bl + gb);
        }
    };

    // ldmatrix lane->(row, chunk) patterns
    const int a_r = lane & 15,                        a_c = lane >> 4;
    const int b_r = (lane & 7) | (((lane >> 4) & 1) << 3), b_c = (lane >> 3) & 1;

    load_stage(0);
    asm volatile("cp.async.commit_group;" ::: "memory");

    for (int kc = 0; kc < NK; kc++) {
        if (kc + 1 < NK) {
            load_stage(kc + 1);
            asm volatile("cp.async.commit_group;" ::: "memory");
            asm volatile("cp.async.wait_group 1;" ::: "memory");
        } else {
            asm volatile("cp.async.wait_group 0;" ::: "memory");
        }
        __syncthreads();
        u32 buf = sb + (kc & 1) * STG;
#pragma unroll
        for (int kh = 0; kh < 2; kh++) {
            u32 ah[4][4], al_[4][4], bh[4][2], bl_[4][2];
#pragma unroll
            for (int s = 0; s < 4; s++) {
                u32 ad = buf + (u32)(wm * 64 + s * 16 + a_r) * 80 + (u32)(kh * 2 + a_c) * 16;
                ldm4(ad,        ah[s][0],  ah[s][1],  ah[s][2],  ah[s][3]);
                ldm4(ad + ARR,  al_[s][0], al_[s][1], al_[s][2], al_[s][3]);
            }
#pragma unroll
            for (int p = 0; p < 2; p++) {
                u32 bd = buf + 2 * ARR + (u32)(wn * 32 + p * 16 + b_r) * 80 + (u32)(kh * 2 + b_c) * 16;
                u32 r0, r1, r2, r3;
                ldm4(bd, r0, r1, r2, r3);
                bh[2*p][0] = r0; bh[2*p][1] = r1; bh[2*p+1][0] = r2; bh[2*p+1][1] = r3;
                ldm4(bd + ARR, r0, r1, r2, r3);
                bl_[2*p][0] = r0; bl_[2*p][1] = r1; bl_[2*p+1][0] = r2; bl_[2*p+1][1] = r3;
            }
#pragma unroll
            for (int s = 0; s < 4; s++)
#pragma unroll
                for (int nf = 0; nf < 4; nf++) {
                    mma16816(acc[s][nf], ah[s],  bh[nf]);
                    mma16816(acc[s][nf], al_[s], bh[nf]);
                    mma16816(acc[s][nf], ah[s],  bl_[nf]);
                }
        }
        __syncthreads();
    }

    const int gr = lane >> 2, tg = lane & 3;
#pragma unroll
    for (int s = 0; s < 4; s++) {
        int rw = m0 + wm * 64 + s * 16 + gr;
#pragma unroll
        for (int nf = 0; nf < 4; nf++) {
            int cc = n0 + wn * 32 + nf * 8 + tg * 2;
            *reinterpret_cast<float2*>(&U[(size_t)rw * NT + cc]) =
                make_float2(acc[s][nf][0], acc[s][nf][1]);
            *reinterpret_cast<float2*>(&U[(size_t)(rw + 8) * NT + cc]) =
                make_float2(acc[s][nf][2], acc[s][nf][3]);
        }
    }
}

// ---------------- Chunked scans (gates computed on the fly) ------------------
__global__ void scan0_A(const float* __restrict__ bf0f, const float* __restrict__ bf0b) {
    int l = blockIdx.x * blockDim.x + threadIdx.x;
    int dj = blockIdx.y; int dir = dj >> 6; int j = dj & 63;
    int b = l >> 8, h = l & 255;
    float bias = (dir ? bf0b : bf0f)[h];
    float a = 1.f, c = 0.f;
    int tb = j * CLEN;
#pragma unroll 8
    for (int s = 0; s < CLEN; s++) {
        int t = dir ? (TT - 1 - (tb + s)) : (tb + s);
        size_t base = ((size_t)t * BB + b) * 1536 + dir * 768 + h;
        float xt = g_U0[base], fp = g_U0[base + 256];
        float f = sigmf(fp + bias);
        c = fmaf(f, c, (1.0f - f) * xt);
        a *= f;
    }
    g_cA0[dir][j * LANES + l] = a;
    g_cB0[dir][j * LANES + l] = c;
}

__global__ void scan0_B(const float* __restrict__ c0) {
    int gi = blockIdx.x * blockDim.x + threadIdx.x;
    int dir = gi >> 13;
    int l = gi & (LANES - 1);
    float c = c0[dir * LANES + l];
#pragma unroll 8
    for (int j = 0; j < NCH; j++) {
        int o = j * LANES + l;
        g_cin0[dir][o] = c;
        c = fmaf(g_cA0[dir][o], c, g_cB0[dir][o]);
    }
}

__global__ void scan0_C(const float* __restrict__ bf0f, const float* __restrict__ bf0b,
                        const float* __restrict__ br0f, const float* __restrict__ br0b) {
    int l = blockIdx.x * blockDim.x + threadIdx.x;
    int dj = blockIdx.y; int dir = dj >> 6; int j = dj & 63;
    int b = l >> 8, h = l & 255;
    float bf = (dir ? bf0b : bf0f)[h];
    float br = (dir ? br0b : br0f)[h];
    float c = g_cin0[dir][j * LANES + l];
    int tb = j * CLEN;
#pragma unroll 4
    for (int s = 0; s < CLEN; s++) {
        int t = dir ? (TT - 1 - (tb + s)) : (tb + s);
        size_t m = (size_t)t * BB + b;
        size_t base = m * 1536 + dir * 768 + h;
        float xt = g_U0[base], fp = g_U0[base + 256], rp = g_U0[base + 512];
        float f = sigmf(fp + bf);
        c = fmaf(f, c, (1.0f - f) * xt);
        float r = sigmf(rp + br);
        size_t i0 = m * HH + h;
        float sk = __bfloat162float(g_x0h[i0]) + __bfloat162float(g_x0l[i0]);
        g_h1[m * (2 * HH) + dir * HH + h] = r * c + (1.0f - r) * sk;
    }
}

__global__ void scan1_A(const float* __restrict__ bf1f) {
    int l = blockIdx.x * blockDim.x + threadIdx.x;
    int j = blockIdx.y;
    int b = l >> 8, h = l & 255;
    float bias = bf1f[h];
    float a = 1.f, c = 0.f;
    int tb = j * CLEN;
#pragma unroll 8
    for (int s = 0; s < CLEN; s++) {
        size_t base = ((size_t)(tb + s) * BB + b) * 512 + h;
        float xt = g_U1[base], fp = g_U1[base + 256];
        float f = sigmf(fp + bias);
        c = fmaf(f, c, (1.0f - f) * xt);
        a *= f;
    }
    g_cA1[j * LANES + l] = a;
    g_cB1[j * LANES + l] = c;
}

__global__ void scan1_B(const float* __restrict__ c0) {
    int l = blockIdx.x * blockDim.x + threadIdx.x;
    float c = c0[2 * LANES + l];
#pragma unroll 8
    for (int j = 0; j < NCH; j++) {
        int o = j * LANES + l;
        c = fmaf(g_cA1[o], c, g_cB1[o]);
    }
    g_cfin[l] = c;
}

// ---------------- Tail: t = T-1 of layer 1 (both dirs) -----------------------
__global__ void tail_h2(const float* __restrict__ W1f,  const float* __restrict__ Wh1f,
                        const float* __restrict__ br1f,
                        const float* __restrict__ W1b,  const float* __restrict__ Wh1b,
                        const float* __restrict__ bf1b, const float* __restrict__ br1b,
                        const float* __restrict__ c0)
{
    __shared__ float xr[2 * HH];
    int b = blockIdx.x;
    int tid = threadIdx.x;
    size_t rowoff = (size_t)((TT - 1) * BB + b) * (2 * HH) + tid;
    xr[tid] = __bfloat162float(g_x1h[rowoff]) + __bfloat162float(g_x1l[rowoff]);
    __syncthreads();
    int h = tid;
    if (h < HH) {
        float ar = 0.f, as = 0.f;
        for (int k = 0; k < 2 * HH; k++) {
            float xv = xr[k];
            ar = fmaf(xv, W1f[k * (3 * HH) + 2 * HH + h], ar);
            as = fmaf(xv, Wh1f[k * HH + h], as);
        }
        float r = sigmf(ar + br1f[h]);
        g_h2[b * (2 * HH) + h] = r * g_cfin[b * HH + h] + (1.0f - r) * as;
    } else {
        int hb = h - HH;
        float a0 = 0.f, a1 = 0.f, a2v = 0.f, as = 0.f;
        for (int k = 0; k < 2 * HH; k++) {
            float xv = xr[k];
            a0  = fmaf(xv, W1b[k * (3 * HH) + hb],          a0);
            a1  = fmaf(xv, W1b[k * (3 * HH) + HH + hb],     a1);
            a2v = fmaf(xv, W1b[k * (3 * HH) + 2 * HH + hb], a2v);
            as  = fmaf(xv, Wh1b[k * HH + hb],               as);
        }
        float f = sigmf(a1 + bf1b[hb]);
        float r = sigmf(a2v + br1b[hb]);
        float c = f * c0[3 * LANES + b * HH + hb] + (1.0f - f) * a0;
        g_h2[b * (2 * HH) + h] = r * c + (1.0f - r) * as;
    }
}

__global__ void tail_out(const float* __restrict__ Wfc,
                         const float* __restrict__ bfc,
                         float* __restrict__ out)
{
    int tid = threadIdx.x;
    int b = tid >> 1, o = tid & 1;
    float acc = bfc[o];
    for (int k = 0; k < 2 * HH; k++)
        acc = fmaf(g_h2[b * (2 * HH) + k], Wfc[k * 2 + o], acc);
    out[b * 2 + o] = acc;
}

// ---------------- launch -------------------------------------------------------
extern "C" void kernel_launch(void* const* d_in, const int* in_sizes, int n_in,
                              void* d_out, int out_size)
{
    const float* x     = (const float*)d_in[0];
    const float* c0    = (const float*)d_in[1];
    const float* ln0_g = (const float*)d_in[2];
    const float* ln0_b = (const float*)d_in[3];
    const float* ln1_g = (const float*)d_in[4];
    const float* ln1_b = (const float*)d_in[5];
    const float* W0f   = (const float*)d_in[6];
    const float* bf0f  = (const float*)d_in[7];
    const float* br0f  = (const float*)d_in[8];
    const float* W0b   = (const float*)d_in[9];
    const float* bf0b  = (const float*)d_in[10];
    const float* br0b  = (const float*)d_in[11];
    const float* W1f   = (const float*)d_in[12];
    const float* Wh1f  = (const float*)d_in[13];
    const float* bf1f  = (const float*)d_in[14];
    const float* br1f  = (const float*)d_in[15];
    const float* W1b   = (const float*)d_in[16];
    const float* Wh1b  = (const float*)d_in[17];
    const float* bf1b  = (const float*)d_in[18];
    const float* br1b  = (const float*)d_in[19];
    const float* Wfc   = (const float*)d_in[20];
    const float* bfc   = (const float*)d_in[21];
    float* out = (float*)d_out;

    const int SMEM = 81920;
    cudaFuncSetAttribute(gemm_hmma<0>, cudaFuncAttributeMaxDynamicSharedMemorySize, SMEM);
    cudaFuncSetAttribute(gemm_hmma<1>, cudaFuncAttributeMaxDynamicSharedMemorySize, SMEM);

    conv_w<<<2560, 256>>>(W0f, W0b, W1f);

    // layer 0
    ln_kernel<256, 0><<<MROWS / 8, 256>>>(x, ln0_g, ln0_b);
    gemm_hmma<0><<<dim3(12, 512), 256, SMEM>>>();
    scan0_A<<<dim3(LANES / 256, 2 * NCH), 256>>>(bf0f, bf0b);
    scan0_B<<<(2 * LANES) / 256, 256>>>(c0);
    scan0_C<<<dim3(LANES / 256, 2 * NCH), 256>>>(bf0f, bf0b, br0f, br0b);

    // layer 1
    ln_kernel<512, 1><<<MROWS / 8, 256>>>(nullptr, ln1_g, ln1_b);
    gemm_hmma<1><<<dim3(4, 512), 256, SMEM>>>();
    scan1_A<<<dim3(LANES / 256, NCH), 256>>>(bf1f);
    scan1_B<<<LANES / 256, 256>>>(c0);

    // tail + head
    tail_h2<<<BB, 2 * HH>>>(W1f, Wh1f, br1f, W1b, Wh1b, bf1b, br1b, c0);
    tail_out<<<1, 64>>>(Wfc, bfc, out);
}